// round 16
// baseline (speedup 1.0000x reference)
#include <cuda_runtime.h>
#include <cuda_bf16.h>

#define S_LEN 512
#define B_DIM 256
#define Z_DIM 64
#define BZ    ((size_t)B_DIM * Z_DIM)

// Per-batch completion counters + likelihood scratch (device globals: no
// allocation; reset each launch by the fwd CTA before any finisher arrives).
__device__ int   g_done[B_DIM];
__device__ float g_invL[B_DIM];

// ---- packed f32x2 helpers (full fp32 precision, 2 MACs per instruction) ----
__device__ __forceinline__ unsigned long long pack2(float lo, float hi) {
    unsigned long long r;
    asm("mov.b64 %0, {%1, %2};" : "=l"(r) : "f"(lo), "f"(hi));
    return r;
}
__device__ __forceinline__ unsigned long long fma2(unsigned long long a,
                                                   unsigned long long b,
                                                   unsigned long long c) {
    unsigned long long d;
    asm("fma.rn.f32x2 %0, %1, %2, %3;" : "=l"(d) : "l"(a), "l"(b), "l"(c));
    return d;
}
__device__ __forceinline__ unsigned long long add2(unsigned long long a,
                                                   unsigned long long b) {
    unsigned long long d;
    asm("add.rn.f32x2 %0, %1, %2;" : "=l"(d) : "l"(a), "l"(b));
    return d;
}
__device__ __forceinline__ float hsum2(unsigned long long v) {
    float lo, hi;
    asm("mov.b64 {%0, %1}, %2;" : "=f"(lo), "=f"(hi) : "l"(v));
    return lo + hi;
}

// FFMA2 dot: 64-float smem vector (16 LDS.128) vs 32 packed T pairs in regs,
// 8 independent f32x2 chains of depth 4 (R12-proven).
#define DOT64(VR, result)                                                      \
    {                                                                          \
        const ulonglong2* p2 = reinterpret_cast<const ulonglong2*>(VR);        \
        unsigned long long s0 = 0, s1 = 0, s2 = 0, s3 = 0,                     \
                           s4 = 0, s5 = 0, s6 = 0, s7 = 0;                     \
        _Pragma("unroll")                                                      \
        for (int q = 0; q < 4; q++) {                                          \
            ulonglong2 u0 = p2[4 * q + 0];                                     \
            ulonglong2 u1 = p2[4 * q + 1];                                     \
            ulonglong2 u2 = p2[4 * q + 2];                                     \
            ulonglong2 u3 = p2[4 * q + 3];                                     \
            s0 = fma2(u0.x, Tp[8 * q + 0], s0);                                \
            s1 = fma2(u0.y, Tp[8 * q + 1], s1);                                \
            s2 = fma2(u1.x, Tp[8 * q + 2], s2);                                \
            s3 = fma2(u1.y, Tp[8 * q + 3], s3);                                \
            s4 = fma2(u2.x, Tp[8 * q + 4], s4);                                \
            s5 = fma2(u2.y, Tp[8 * q + 5], s5);                                \
            s6 = fma2(u3.x, Tp[8 * q + 6], s6);                                \
            s7 = fma2(u3.y, Tp[8 * q + 7], s7);                                \
        }                                                                      \
        unsigned long long sA = add2(add2(s0, s1), add2(s2, s3));              \
        unsigned long long sB = add2(add2(s4, s5), add2(s6, s7));              \
        result = hsum2(add2(sA, sB));                                          \
    }

// ---------------------------------------------------------------------------
// R12's fused fwd/bwd recursion (512 CTAs x 64 thr) + in-kernel posterior:
// the SECOND finisher of each (fwd b, bwd b) pair normalizes batch b's
// posterior elementwise with invL = 1/sum_z(alpha[511]) — reads hit L2.
// ---------------------------------------------------------------------------
__global__ __launch_bounds__(Z_DIM)
void hmm_fb_kernel(const int* __restrict__ inp,      // [S, B]
                   const float* __restrict__ T,      // [Z, Z]
                   const float* __restrict__ pi,     // [Z]
                   const float* __restrict__ emit,   // [X, Z]
                   float* __restrict__ alpha,        // [S, B, Z]
                   float* __restrict__ beta,         // [S, B, Z]
                   float* __restrict__ post)         // [S, B, Z]
{
    const bool bwd = blockIdx.x >= B_DIM;
    const int  b   = blockIdx.x & (B_DIM - 1);
    const int  z   = threadIdx.x;

    // Reset this batch's flag (finishers arrive ~100us later; all CTAs
    // co-resident from launch, so this cannot race with them).
    if (!bwd && z == 0) atomicExch(&g_done[b], 0);

    __shared__ __align__(16) float v_sh[2][Z_DIM];
    __shared__ int   x_sh[S_LEN];
    __shared__ float ls[2];
    __shared__ int   old_sh;

    #pragma unroll
    for (int t = z; t < S_LEN; t += Z_DIM) x_sh[t] = inp[t * B_DIM + b];

    // T packed K-pairwise: fwd row z, bwd column z.
    unsigned long long Tp[Z_DIM / 2];
    if (!bwd) {
        #pragma unroll
        for (int k = 0; k < Z_DIM; k += 4) {
            float4 v = *reinterpret_cast<const float4*>(&T[z * Z_DIM + k]);
            Tp[k / 2]     = pack2(v.x, v.y);
            Tp[k / 2 + 1] = pack2(v.z, v.w);
        }
    } else {
        #pragma unroll
        for (int k = 0; k < Z_DIM; k += 2) {
            Tp[k / 2] = pack2(T[k * Z_DIM + z], T[(k + 1) * Z_DIM + z]);
        }
    }
    __syncthreads();            // x_sh visible before any use

    if (!bwd) {
        // ---------------- forward ----------------
        float* aw = alpha + (size_t)b * Z_DIM;
        float a0 = emit[x_sh[0] * Z_DIM + z] * pi[z];
        v_sh[0][z] = a0;
        float  f_pend = a0;
        size_t f_pofs = z;                       // alpha[0]
        float eo = emit[x_sh[1] * Z_DIM + z];    // e for odd steps
        float ee = emit[x_sh[2] * Z_DIM + z];    // e for even steps
        __syncthreads();

#define FWD_STEP(t, VR, VW, E)                                                 \
    {                                                                          \
        float d; DOT64(VR, d);                                                 \
        float n = (E) * d;                                                     \
        (VW)[z] = n;                                                           \
        __syncthreads();                                                       \
        aw[f_pofs] = f_pend;                                                   \
        f_pend = n; f_pofs = (size_t)(t) * BZ + z;                             \
        int xp = x_sh[((t) + 2 < S_LEN) ? (t) + 2 : S_LEN - 1] * Z_DIM;        \
        E = emit[xp + z];                                                      \
    }

        for (int t = 1; t < S_LEN - 1; t += 2) {
            FWD_STEP(t,     v_sh[0], v_sh[1], eo);
            FWD_STEP(t + 1, v_sh[1], v_sh[0], ee);
        }
        // tail t = 511 (odd; reads v_sh[510&1=0], e in eo)
        {
            float d; DOT64(v_sh[0], d);
            float nf = eo * d;                   // alpha[511][z]
            aw[f_pofs] = f_pend;                 // alpha[510]
            aw[(size_t)(S_LEN - 1) * BZ + z] = nf;
            // likelihood: L = sum_z alpha[511] (beta[511] = 1)
            float s = nf;
            #pragma unroll
            for (int o = 16; o > 0; o >>= 1)
                s += __shfl_xor_sync(0xffffffffu, s, o);
            if ((z & 31) == 0) ls[z >> 5] = s;
            __syncthreads();
            if (z == 0) g_invL[b] = 1.0f / (ls[0] + ls[1]);
        }
#undef FWD_STEP
    } else {
        // ---------------- backward ----------------
        float* bw = beta + (size_t)b * Z_DIM;
        v_sh[1][z] = emit[x_sh[S_LEN - 1] * Z_DIM + z];  // c[511] (511&1==1)
        float  b_pend = 1.0f;
        size_t b_pofs = (size_t)(S_LEN - 1) * BZ + z;    // beta[511]
        float ee = emit[x_sh[S_LEN - 2] * Z_DIM + z];    // e for even steps
        float eo = emit[x_sh[S_LEN - 3] * Z_DIM + z];    // e for odd steps
        __syncthreads();

#define BWD_STEP(t, VR, VW, E)                                                 \
    {                                                                          \
        float d; DOT64(VR, d);                                                 \
        (VW)[z] = (E) * d;                                                     \
        __syncthreads();                                                       \
        bw[b_pofs] = b_pend;                                                   \
        b_pend = d; b_pofs = (size_t)(t) * BZ + z;                             \
        int xp = x_sh[((t) >= 2) ? (t) - 2 : 0] * Z_DIM;                       \
        E = emit[xp + z];                                                      \
    }

        for (int t = S_LEN - 2; t >= 2; t -= 2) {
            BWD_STEP(t,     v_sh[1], v_sh[0], ee);   // even t: buf1 -> buf0
            BWD_STEP(t - 1, v_sh[0], v_sh[1], eo);   // odd  t: buf0 -> buf1
        }
        bw[b_pofs] = b_pend;                         // beta[1]
        {   // t = 0: beta only (reads c[1] in buf1)
            float d; DOT64(v_sh[1], d);
            bw[z] = d;                               // beta[0]
        }
#undef BWD_STEP
    }

    // ---------------- completion handoff + fused posterior ----------------
    __threadfence();                 // publish this CTA's alpha/beta (+invL)
    if (z == 0) old_sh = atomicAdd(&g_done[b], 1);
    __syncthreads();
    if (old_sh == 1) {               // second finisher: both halves complete
        __threadfence();             // acquire the other CTA's stores
        const float invL = g_invL[b];
        const int c4 = (z & 15) * 4;     // float4 column
        const int r0 = z >> 4;           // starting row (0..3)
        const size_t base = (size_t)b * Z_DIM + c4;
        #pragma unroll 4
        for (int t = r0; t < S_LEN; t += 4) {
            const size_t off = (size_t)t * BZ + base;
            float4 av = __ldcg(reinterpret_cast<const float4*>(alpha + off));
            float4 bv = __ldcg(reinterpret_cast<const float4*>(beta  + off));
            float4 p;
            p.x = av.x * bv.x * invL;
            p.y = av.y * bv.y * invL;
            p.z = av.z * bv.z * invL;
            p.w = av.w * bv.w * invL;
            __stcs(reinterpret_cast<float4*>(post + off), p);
        }
    }
}

extern "C" void kernel_launch(void* const* d_in, const int* in_sizes, int n_in,
                              void* d_out, int out_size)
{
    const int*   inp  = (const int*)  d_in[0];   // [512, 256] int32
    const float* T    = (const float*)d_in[1];   // [64, 64]
    const float* pi   = (const float*)d_in[2];   // [64]
    const float* emit = (const float*)d_in[3];   // [10000, 64]

    float* out   = (float*)d_out;
    const size_t N = (size_t)S_LEN * B_DIM * Z_DIM;
    float* alpha = out;
    float* beta  = out + N;
    float* post  = out + 2 * N;

    hmm_fb_kernel<<<2 * B_DIM, Z_DIM>>>(inp, T, pi, emit, alpha, beta, post);
}